// round 17
// baseline (speedup 1.0000x reference)
#include <cuda_runtime.h>
#include <cuda_bf16.h>
#include <cstdint>
#include <math.h>

#define T_STEPS 2048
#define B_ROWS  64
#define TNO     501
#define NBASIS  30
#define ACC_N   512     // far-delay accumulator ring (power of 2 > TNO)
#define ACC_M   511
#define NTH     128     // 4 warps: key-chain / sub+uniform / decision / scatter

// ---------------------------------------------------------------------------
// Threefry-2x32, 20 rounds — bit-exact port of jax/_src/prng.py threefry2x32
// ---------------------------------------------------------------------------
__device__ __forceinline__ void tf2x32(uint32_t k0, uint32_t k1,
                                       uint32_t x0, uint32_t x1,
                                       uint32_t &o0, uint32_t &o1) {
    uint32_t k2 = k0 ^ k1 ^ 0x1BD11BDAu;
#define TFR(r) { x0 += x1; x1 = __funnelshift_l(x1, x1, (r)); x1 ^= x0; }
    x0 += k0; x1 += k1;
    TFR(13) TFR(15) TFR(26) TFR(6)
    x0 += k1; x1 += k2 + 1u;
    TFR(17) TFR(29) TFR(16) TFR(24)
    x0 += k2; x1 += k0 + 2u;
    TFR(13) TFR(15) TFR(26) TFR(6)
    x0 += k0; x1 += k1 + 3u;
    TFR(17) TFR(29) TFR(16) TFR(24)
    x0 += k1; x1 += k2 + 4u;
    TFR(13) TFR(15) TFR(26) TFR(6)
    x0 += k2; x1 += k0 + 5u;
#undef TFR
    o0 = x0; o1 = x1;
}

// XLA EmitTanh (Eigen rational, clamp [-9,9], |x|<4e-4 -> x), UNcontracted.
// This exact form gave rel_err 8e-8 (zero Bernoulli flips). DO NOT TOUCH.
__device__ __forceinline__ float tanh_xla(float x) {
    float ax = fabsf(x);
    float xc = fminf(fmaxf(x, -9.0f), 9.0f);
    float x2 = __fmul_rn(xc, xc);
    float num = -2.76076847742355e-16f;
    num = __fadd_rn(__fmul_rn(x2, num),  2.00018790482477e-13f);
    num = __fadd_rn(__fmul_rn(x2, num), -8.60467152213735e-11f);
    num = __fadd_rn(__fmul_rn(x2, num),  5.12229709037114e-08f);
    num = __fadd_rn(__fmul_rn(x2, num),  1.48572235717979e-05f);
    num = __fadd_rn(__fmul_rn(x2, num),  6.37261928875436e-04f);
    num = __fadd_rn(__fmul_rn(x2, num),  4.89352455891786e-03f);
    num = __fmul_rn(xc, num);
    float den = 1.19825839466702e-06f;
    den = __fadd_rn(__fmul_rn(x2, den),  1.18534705686654e-04f);
    den = __fadd_rn(__fmul_rn(x2, den),  2.26843463243900e-03f);
    den = __fadd_rn(__fmul_rn(x2, den),  4.89352518554385e-03f);
    float r = __fdiv_rn(num, den);
    return (ax < 0.0004f) ? x : r;
}
// P = 0.5*tanh(0.5*x)+0.5  (bit-identical to the passing kernel's sequence)
__device__ __forceinline__ float sigP(float x) {
    return __fadd_rn(__fmul_rn(0.5f, tanh_xla(__fmul_rn(0.5f, x))), 0.5f);
}

__device__ __forceinline__ void st_rel(int *p, int v) {
    uint32_t a = (uint32_t)__cvta_generic_to_shared(p);
    asm volatile("st.release.cta.shared.b32 [%0], %1;" :: "r"(a), "r"(v) : "memory");
}
__device__ __forceinline__ int ldv(volatile int *p) { return *p; }

// ---------------------------------------------------------------------------
// One block per row b.  4 warps:
//   warp0 lane0   : key chain: key <- tf(key,(0,0)) — ~185 cy/step, the pacer
//   warp1 lanes0-3: sub+uniform: sub = tf(key,(0,1)); u = tf(sub,(0,b))
//   warp2 (all 32): decision — lane L = candidate P(t|mask=L), ballot W[t].
//                   SOFTWARE-PIPELINED: slot t computes x(t); sigP/ballot of
//                   x(t-2) runs in the same slot as an independent chain.
//                   Resolve of s(t-5) = pure bit-ops (validated R15 sequence).
//   warp3 (all 32): scatter — consumes per-batch 8-bit spike masks; a full
//                   batch of slack before its output is needed back.
// ---------------------------------------------------------------------------
__global__ __launch_bounds__(NTH)
void apnn_kernel(const float *__restrict__ V,  const float *__restrict__ D,
                 const float *__restrict__ w1, const float *__restrict__ b1,
                 const float *__restrict__ w2, const float *__restrict__ b2,
                 const float *__restrict__ Wref, float *__restrict__ out) {
    __shared__ __align__(16) float nnrow[T_STEPS];   // MLP output
    __shared__ __align__(16) float uring[T_STEPS];   // uniforms
    __shared__ __align__(16) float acc[ACC_N];       // pending far refract
    __shared__ uint32_t keyring[T_STEPS][2];         // key_t (pre-split)
    __shared__ float    wdel[TNO];                   // weight for delay j+1
    __shared__ int      spmask[T_STEPS / 8];         // per-batch spike masks
    __shared__ int      chain_seq, u_seq, dec_seq, scatter_seq;

    const int tid = threadIdx.x;
    const int wid = tid >> 5;
    const int b   = blockIdx.x;

    if (tid == 0) { chain_seq = 0; u_seq = 0; dec_seq = 0; scatter_seq = 0; }
    __syncthreads();

    if (tid == 0) {
        // ---- key chain: ONLY key <- tf(key,(0,0))  (R15 verbatim)
        uint32_t k0 = 0u, k1 = 42u;              // jax.random.key(42) -> (0,42)
        for (int base = 0; base < T_STEPS; base += 4) {
            #pragma unroll
            for (int q = 0; q < 4; q++) {
                keyring[base + q][0] = k0;
                keyring[base + q][1] = k1;
                uint32_t nk0, nk1;
                tf2x32(k0, k1, 0u, 0u, nk0, nk1);
                k0 = nk0; k1 = nk1;
            }
            st_rel(&chain_seq, base + 4);
        }
    } else if (tid >= 32 && tid < 36) {
        // ---- sub+uniform (R15 verbatim)
        const int lane = tid - 32;
        int cs = 0;
        for (int base = 0; base < T_STEPS; base += 4) {
            if (cs < base + 4) { do { cs = ldv(&chain_seq); } while (cs < base + 4); }
            int t = base + lane;
            uint32_t k0 = keyring[t][0];
            uint32_t k1 = keyring[t][1];
            uint32_t s0, s1, y0, y1;
            tf2x32(k0, k1, 0u, 1u, s0, s1);          // sub_t = tf(key,(0,1))
            tf2x32(s0, s1, 0u, (uint32_t)b, y0, y1); // bits = tf(sub,(0,b))
            uint32_t bits = y0 ^ y1;
            uring[t] = __uint_as_float((bits >> 9) | 0x3F800000u) - 1.0f;
            __syncwarp(0xFu);
            if (lane == 0) st_rel(&u_seq, base + 4);
        }
    } else if (tid >= 64) {
        // ---- init on warps 2+3 (64 threads), overlapped with chain/uniform
        const int itid = tid - 64;
        for (int i = itid; i < ACC_N; i += 64) acc[i] = 0.0f;
        for (int j = itid; j < TNO; j += 64) {
            double raw = 7.5 * log(((double)j + 1.0) + 1e-7);
            double cr = cos(raw), sr = sin(raw);
            float s = 0.0f;
            #pragma unroll 1
            for (int i = 0; i < NBASIS; i++) {
                double phi = 1.5707963267948966 * (double)i;
                float bas = 0.0f;
                if (!(raw < phi - 3.141592653589793 || raw > phi + 3.141592653589793)) {
                    double cv;
                    switch (i & 3) {
                        case 0:  cv =  cr; break;
                        case 1:  cv =  sr; break;
                        case 2:  cv = -cr; break;
                        default: cv = -sr; break;
                    }
                    bas = (float)(0.5 * cv + 0.5);
                }
                s = __fmaf_rn(bas, Wref[i], s);
            }
            wdel[j] = s;
        }
        {
            float a0 = w1[0], a1 = w1[1], a2 = w1[2], a3 = w1[3], a4 = w1[4];
            float a5 = w1[5], a6 = w1[6], a7 = w1[7], a8 = w1[8], a9 = w1[9];
            float c0 = b1[0], c1 = b1[1], c2 = b1[2], c3 = b1[3], c4 = b1[4];
            float v0 = w2[0], v1 = w2[1], v2 = w2[2], v3 = w2[3], v4 = w2[4];
            float bb = b2[0];
            const float *Vr = V + (size_t)b * T_STEPS;
            const float *Dr = D + (size_t)b * T_STEPS;
            for (int t = itid; t < T_STEPS; t += 64) {
                float vv = Vr[t], dd = Dr[t];
                float h0 = tanh_xla(__fadd_rn(__fadd_rn(__fmul_rn(a0, vv), __fmul_rn(a1, dd)), c0));
                float h1 = tanh_xla(__fadd_rn(__fadd_rn(__fmul_rn(a2, vv), __fmul_rn(a3, dd)), c1));
                float h2 = tanh_xla(__fadd_rn(__fadd_rn(__fmul_rn(a4, vv), __fmul_rn(a5, dd)), c2));
                float h3 = tanh_xla(__fadd_rn(__fadd_rn(__fmul_rn(a6, vv), __fmul_rn(a7, dd)), c3));
                float h4 = tanh_xla(__fadd_rn(__fadd_rn(__fmul_rn(a8, vv), __fmul_rn(a9, dd)), c4));
                float s = __fmul_rn(v0, h0);
                s = __fadd_rn(s, __fmul_rn(v1, h1));
                s = __fadd_rn(s, __fmul_rn(v2, h2));
                s = __fadd_rn(s, __fmul_rn(v3, h3));
                s = __fadd_rn(s, __fmul_rn(v4, h4));
                nnrow[t] = __fadd_rn(s, bb);
            }
        }
        asm volatile("bar.sync 1, 64;" ::: "memory");   // warps 2+3

        if (wid == 2) {
            // ================= decision warp (pipelined) =================
            const int lane = tid & 31;
            const bool cb0 = lane & 1, cb1 = lane & 2, cb2 = lane & 4,
                       cb3 = lane & 8, cb4 = lane & 16;
            const float wd0 = wdel[0],  wd1 = wdel[1],  wd2 = wdel[2];
            const float wd3 = wdel[3],  wd4 = wdel[4],  wd5 = wdel[5];
            const float wd6 = wdel[6],  wd7 = wdel[7],  wd8 = wdel[8];
            const float wd9 = wdel[9],  wd10 = wdel[10], wd11 = wdel[11];
            float g6 = 0.f, g7 = 0.f, g8 = 0.f, g9 = 0.f,
                  g10 = 0.f, g11 = 0.f, g12 = 0.f;
            float    xr[8];                       // x(t) ring (static idx)
            float    Pc[8];                       // candidate P ring
            uint32_t Wb[8];                       // ballot ring
            #pragma unroll
            for (int i = 0; i < 8; i++) { xr[i] = 0.f; Pc[i] = 0.f; Wb[i] = 0u; }
            float sp_prev6 = 0.f;                 // s(t-6)
            unsigned m = 0;                       // realized 5-bit mask
            float ucar0 = 0.f, ucar1 = 0.f;       // u(B-2), u(B-1) carry
            float *Sout = out + (size_t)b * T_STEPS;
            float *Pout = out + (size_t)B_ROWS * T_STEPS + (size_t)b * T_STEPS;
            int us = 0, ss = 0;
            for (int B = 0; B < T_STEPS; B += 8) {
                if (us < B + 8) { do { us = ldv(&u_seq); } while (us < B + 8); }
                if (ss < B)     { do { ss = ldv(&scatter_seq); } while (ss < B); }
                // vectorized batch prefetch
                float4 ua = *reinterpret_cast<const float4*>(&uring[B]);
                float4 ub = *reinterpret_cast<const float4*>(&uring[B + 4]);
                float4 na = *reinterpret_cast<const float4*>(&nnrow[B]);
                float4 nb = *reinterpret_cast<const float4*>(&nnrow[B + 4]);
                int    ab = B & ACC_M;
                float4 fa = *reinterpret_cast<const float4*>(&acc[ab]);
                float4 fb = *reinterpret_cast<const float4*>(&acc[ab + 4]);
                if (lane == 0) {
                    float4 z = make_float4(0.f, 0.f, 0.f, 0.f);
                    *reinterpret_cast<float4*>(&acc[ab])     = z;
                    *reinterpret_cast<float4*>(&acc[ab + 4]) = z;
                }
                // compare-u per slot p uses tau = B+p-2
                float uu[8] = {ucar0, ucar1, ua.x, ua.y, ua.z, ua.w, ub.x, ub.y};
                ucar0 = ub.z; ucar1 = ub.w;
                float nnv[8] = {na.x, na.y, na.z, na.w, nb.x, nb.y, nb.z, nb.w};
                float fr[8]  = {fa.x, fa.y, fa.z, fa.w, fb.x, fb.y, fb.z, fb.w};
                float myS = 0.f, myP = 0.f;
                unsigned bmask = 0u;
                #pragma unroll
                for (int p = 0; p < 8; p++) {
                    const int t = B + p;
                    // --- stage A: resolve s(t-5) (bit-ops; validated seq) ---
                    unsigned mo    = m;
                    unsigned spbit = (Wb[(p + 3) & 7] >> mo) & 1u;
                    spbit &= (unsigned)(t >= 5);            // t5<0 -> 0
                    m = ((mo << 1) | spbit) & 31u;
                    float spf = spbit ? 1.0f : 0.0f;
                    float Pv = __shfl_sync(0xFFFFFFFFu, Pc[(p + 3) & 7], (int)mo);
                    if (lane == p) { myS = spf; myP = Pv; }
                    bmask |= spbit << p;
                    // --- stage A2: g tail with s(t-6) ---
                    g6  = __fmaf_rn(wd5,  sp_prev6, g7);
                    g7  = __fmaf_rn(wd6,  sp_prev6, g8);
                    g8  = __fmaf_rn(wd7,  sp_prev6, g9);
                    g9  = __fmaf_rn(wd8,  sp_prev6, g10);
                    g10 = __fmaf_rn(wd9,  sp_prev6, g11);
                    g11 = __fmaf_rn(wd10, sp_prev6, g12);
                    g12 = __fmul_rn(wd11, sp_prev6);
                    sp_prev6 = spf;
                    // --- stage A3: x(t) (validated sequence) ---
                    float v = g6;
                    if (cb4) v = __fadd_rn(wd4, v);
                    if (cb3) v = __fadd_rn(wd3, v);
                    if (cb2) v = __fadd_rn(wd2, v);
                    if (cb1) v = __fadd_rn(wd1, v);
                    if (cb0) v = __fadd_rn(wd0, v);
                    xr[p] = __fadd_rn(nnv[p], __fadd_rn(fr[p], v));
                    // --- stage B: sigP + ballot for tau = t-2 (independent) ---
                    float P = sigP(xr[(p + 6) & 7]);
                    Pc[(p + 6) & 7] = P;
                    bool spc = (uu[p] < P);
                    Wb[(p + 6) & 7] = __ballot_sync(0xFFFFFFFFu, spc);
                }
                // batch outputs + spike-mask publish
                {
                    int to = B + lane - 5;
                    if (lane < 8 && to >= 0) { Sout[to] = myS; Pout[to] = myP; }
                }
                if (lane == 0) {
                    spmask[B >> 3] = (int)bmask;
                    st_rel(&dec_seq, B + 8);
                }
            }
            // ---- epilogue: sigP for tau = T-2, T-1; resolve t5 = T-5..T-1
            #pragma unroll
            for (int e = 0; e < 2; e++) {
                int tau = T_STEPS - 2 + e;
                float P = sigP(xr[tau & 7]);
                Pc[tau & 7] = P;
                bool spc = (uring[tau] < P);
                Wb[tau & 7] = __ballot_sync(0xFFFFFFFFu, spc);
            }
            #pragma unroll
            for (int e = 0; e < 5; e++) {
                int t5 = T_STEPS - 5 + e;
                int idx = t5 & 7;
                unsigned mo    = m;
                unsigned spbit = (Wb[idx] >> mo) & 1u;
                m = ((mo << 1) | spbit) & 31u;
                float Pv = __shfl_sync(0xFFFFFFFFu, Pc[idx], (int)mo);
                if (lane == 0) {
                    Sout[t5] = spbit ? 1.0f : 0.0f;
                    Pout[t5] = Pv;
                }
            }
        } else {
            // ================= scatter warp (batched, slack-rich) ==========
            const int lane = tid - 96;
            float wreg[16];                       // far delays d = 13+lane+32j
            #pragma unroll
            for (int j = 0; j < 16; j++) {
                int d = 13 + lane + 32 * j;
                wreg[j] = (d <= TNO) ? wdel[d - 1] : 0.0f;
            }
            int ds = 0;
            for (int B = 0; B < T_STEPS; B += 8) {
                if (ds < B + 8) { do { ds = ldv(&dec_seq); } while (ds < B + 8); }
                unsigned mask = (unsigned)spmask[B >> 3];
                #pragma unroll
                for (int p = 0; p < 8; p++) {
                    if ((mask >> p) & 1u) {
                        int t5 = B + p - 5;
                        #pragma unroll
                        for (int j = 0; j < 16; j++) {
                            int d = 13 + lane + 32 * j;
                            if (d <= TNO) {
                                int sl = (t5 + d) & ACC_M;   // conflict-free
                                acc[sl] = __fmaf_rn(wreg[j], 1.0f, acc[sl]);
                            }
                        }
                    }
                }
                __syncwarp();
                if (lane == 0) st_rel(&scatter_seq, B + 8);
            }
        }
    }
}

extern "C" void kernel_launch(void* const* d_in, const int* in_sizes, int n_in,
                              void* d_out, int out_size) {
    const float *V    = (const float*)d_in[0];
    const float *D    = (const float*)d_in[1];
    const float *w1   = (const float*)d_in[2];
    const float *b1   = (const float*)d_in[3];
    const float *w2   = (const float*)d_in[4];
    const float *b2   = (const float*)d_in[5];
    const float *Wref = (const float*)d_in[6];
    float *out = (float*)d_out;
    apnn_kernel<<<B_ROWS, NTH>>>(V, D, w1, b1, w2, b2, Wref, out);
}